// round 12
// baseline (speedup 1.0000x reference)
#include <cuda_runtime.h>

// Collapsed math: out[b,c] = softmax_c( d*r/1000 + d + r ),
// r = x[b,0,c], d = x[b,1,c]; logits in [0, 2.001] -> no max pass needed.
//
// Warp-per-row, 64-thread CTAs (2 rows/CTA), grid 32768:
//   - finest CTA granularity for work-distributor backfill (monotone win:
//     888->119.6, 4096->117.4, 8192->112.4, 16384->110.9 us kernel time)
//   - 32 CTA slots x 2 warps = 64 resident warps/SM at regs=48: occ unchanged
//   - one warp owns one full row (250 float4 = 1000 classes)
//   - iterations 0..6 unconditional; only iter 7 predicated (lane < 26)
//   - warp-only shfl reduction; no smem, no __syncthreads
//   - __ldcs/__stcs streaming hints (zero-reuse stream), 16B accesses

#define NUM_CLASSES 1000
#define VEC_PER_ROW (NUM_CLASSES / 4)      // 250 float4 per row per tensor
#define ROW_VEC_STRIDE (2 * VEC_PER_ROW)   // 500 float4 per (2,1000) row
#define THREADS 64
#define ROWS_PER_CTA (THREADS / 32)        // 2
#define FULL_ITERS 7                       // lane + 32*6 = 223 < 250 always

__device__ __forceinline__ float4 ev4(float4 r, float4 d)
{
    float4 e;
    e.x = __expf(fmaf(d.x * r.x, 1e-3f, d.x + r.x));
    e.y = __expf(fmaf(d.y * r.y, 1e-3f, d.y + r.y));
    e.z = __expf(fmaf(d.z * r.z, 1e-3f, d.z + r.z));
    e.w = __expf(fmaf(d.w * r.w, 1e-3f, d.w + r.w));
    return e;
}

__global__ __launch_bounds__(THREADS) void tmc_softmax_warprow(
    const float4* __restrict__ x4, float4* __restrict__ out4)
{
    const int warp = threadIdx.x >> 5;
    const int lane = threadIdx.x & 31;
    const size_t row = (size_t)blockIdx.x * ROWS_PER_CTA + warp;

    const float4* __restrict__ rgb = x4 + row * ROW_VEC_STRIDE;
    const float4* __restrict__ dep = rgb + VEC_PER_ROW;
    float4* __restrict__ out = out4 + row * VEC_PER_ROW;

    const bool tail = (lane + 32 * FULL_ITERS) < VEC_PER_ROW;   // lane < 26

    float4 ev[FULL_ITERS + 1];
    float local = 0.f;

    #pragma unroll
    for (int i = 0; i < FULL_ITERS; i++) {
        const int idx = lane + 32 * i;
        float4 e = ev4(__ldcs(&rgb[idx]), __ldcs(&dep[idx]));
        ev[i] = e;
        local += (e.x + e.y) + (e.z + e.w);
    }
    if (tail) {
        const int idx = lane + 32 * FULL_ITERS;
        float4 e = ev4(__ldcs(&rgb[idx]), __ldcs(&dep[idx]));
        ev[FULL_ITERS] = e;
        local += (e.x + e.y) + (e.z + e.w);
    }

    // Warp-only reduction: no barriers, no smem.
    #pragma unroll
    for (int off = 16; off > 0; off >>= 1)
        local += __shfl_xor_sync(0xFFFFFFFFu, local, off);

    const float inv = 1.0f / local;

    #pragma unroll
    for (int i = 0; i < FULL_ITERS; i++) {
        const int idx = lane + 32 * i;
        float4 o;
        o.x = ev[i].x * inv;
        o.y = ev[i].y * inv;
        o.z = ev[i].z * inv;
        o.w = ev[i].w * inv;
        __stcs(&out[idx], o);
    }
    if (tail) {
        const int idx = lane + 32 * FULL_ITERS;
        float4 o;
        o.x = ev[FULL_ITERS].x * inv;
        o.y = ev[FULL_ITERS].y * inv;
        o.z = ev[FULL_ITERS].z * inv;
        o.w = ev[FULL_ITERS].w * inv;
        __stcs(&out[idx], o);
    }
}

extern "C" void kernel_launch(void* const* d_in, const int* in_sizes, int n_in,
                              void* d_out, int out_size)
{
    const float4* x4 = (const float4*)d_in[0];
    float4* out4 = (float4*)d_out;
    const int batch = in_sizes[0] / (2 * NUM_CLASSES);   // 65536
    tmc_softmax_warprow<<<batch / ROWS_PER_CTA, THREADS>>>(x4, out4);
}

// round 13
// speedup vs baseline: 1.0047x; 1.0047x over previous
#include <cuda_runtime.h>

// Collapsed math: out[b,c] = softmax_c( d*r/1000 + d + r ),
// r = x[b,0,c], d = x[b,1,c]; logits in [0, 2.001] -> no max pass needed.
//
// CTA-per-row, 32-thread CTAs (1 warp), grid 65536 — endpoint of the
// granularity sweep (kernel time: 888->119.6, 4096->117.4, 8192->112.4,
// 16384->110.9, 32768->110.1 us). 32 CTA slots x 1 warp = 32 warps/SM,
// same occupancy as the 64-thread variant (measured 50%), but maximal
// scheduling granularity and zero CTA-retire tail imbalance.
//   - one warp owns one full row (250 float4 = 1000 classes)
//   - iterations 0..6 unconditional; only iter 7 predicated (lane < 26)
//   - warp-only shfl reduction; no smem, no __syncthreads
//   - __ldcs/__stcs streaming hints (zero-reuse stream), 16B accesses

#define NUM_CLASSES 1000
#define VEC_PER_ROW (NUM_CLASSES / 4)      // 250 float4 per row per tensor
#define ROW_VEC_STRIDE (2 * VEC_PER_ROW)   // 500 float4 per (2,1000) row
#define THREADS 32
#define FULL_ITERS 7                       // lane + 32*6 = 223 < 250 always

__device__ __forceinline__ float4 ev4(float4 r, float4 d)
{
    float4 e;
    e.x = __expf(fmaf(d.x * r.x, 1e-3f, d.x + r.x));
    e.y = __expf(fmaf(d.y * r.y, 1e-3f, d.y + r.y));
    e.z = __expf(fmaf(d.z * r.z, 1e-3f, d.z + r.z));
    e.w = __expf(fmaf(d.w * r.w, 1e-3f, d.w + r.w));
    return e;
}

__global__ __launch_bounds__(THREADS) void tmc_softmax_warprow(
    const float4* __restrict__ x4, float4* __restrict__ out4)
{
    const int lane = threadIdx.x;
    const size_t row = blockIdx.x;

    const float4* __restrict__ rgb = x4 + row * ROW_VEC_STRIDE;
    const float4* __restrict__ dep = rgb + VEC_PER_ROW;
    float4* __restrict__ out = out4 + row * VEC_PER_ROW;

    const bool tail = (lane + 32 * FULL_ITERS) < VEC_PER_ROW;   // lane < 26

    float4 ev[FULL_ITERS + 1];
    float local = 0.f;

    #pragma unroll
    for (int i = 0; i < FULL_ITERS; i++) {
        const int idx = lane + 32 * i;
        float4 e = ev4(__ldcs(&rgb[idx]), __ldcs(&dep[idx]));
        ev[i] = e;
        local += (e.x + e.y) + (e.z + e.w);
    }
    if (tail) {
        const int idx = lane + 32 * FULL_ITERS;
        float4 e = ev4(__ldcs(&rgb[idx]), __ldcs(&dep[idx]));
        ev[FULL_ITERS] = e;
        local += (e.x + e.y) + (e.z + e.w);
    }

    // Warp-only reduction: no barriers, no smem.
    #pragma unroll
    for (int off = 16; off > 0; off >>= 1)
        local += __shfl_xor_sync(0xFFFFFFFFu, local, off);

    const float inv = 1.0f / local;

    #pragma unroll
    for (int i = 0; i < FULL_ITERS; i++) {
        const int idx = lane + 32 * i;
        float4 o;
        o.x = ev[i].x * inv;
        o.y = ev[i].y * inv;
        o.z = ev[i].z * inv;
        o.w = ev[i].w * inv;
        __stcs(&out[idx], o);
    }
    if (tail) {
        const int idx = lane + 32 * FULL_ITERS;
        float4 o;
        o.x = ev[FULL_ITERS].x * inv;
        o.y = ev[FULL_ITERS].y * inv;
        o.z = ev[FULL_ITERS].z * inv;
        o.w = ev[FULL_ITERS].w * inv;
        __stcs(&out[idx], o);
    }
}

extern "C" void kernel_launch(void* const* d_in, const int* in_sizes, int n_in,
                              void* d_out, int out_size)
{
    const float4* x4 = (const float4*)d_in[0];
    float4* out4 = (float4*)d_out;
    const int batch = in_sizes[0] / (2 * NUM_CLASSES);   // 65536
    tmc_softmax_warprow<<<batch, THREADS>>>(x4, out4);
}

// round 14
// speedup vs baseline: 1.0072x; 1.0025x over previous
#include <cuda_runtime.h>

// Collapsed math: out[b,c] = softmax_c( d*r/1000 + d + r ),
// r = x[b,0,c], d = x[b,1,c]; logits in [0, 2.001] -> no max pass needed.
//
// CTA-per-row (32 threads, grid 65536) + Blackwell 256-bit global accesses:
//   - ld/st.global.cs.v8.f32: 32B per lane, 1024B per warp request
//     (all bases 32B-aligned: row strides 8000/4000 bytes)
//   - 125 float8 per row per tensor: 3 unconditional iters + tail (lane<29)
//   - warp-only shfl reduction; no smem, no __syncthreads
//   - .cs streaming (zero-reuse stream)

#define NUM_CLASSES 1000
#define V8_PER_ROW (NUM_CLASSES / 8)       // 125 float8 per row per tensor
#define ROW_F_STRIDE (2 * NUM_CLASSES)     // 2000 floats per (2,1000) row
#define THREADS 32
#define FULL_ITERS 3                       // lane + 32*2 = 95 < 125 always

__device__ __forceinline__ void ldg256_cs(const float* p, float* v)
{
    asm("ld.global.cs.v8.f32 {%0,%1,%2,%3,%4,%5,%6,%7}, [%8];"
        : "=f"(v[0]), "=f"(v[1]), "=f"(v[2]), "=f"(v[3]),
          "=f"(v[4]), "=f"(v[5]), "=f"(v[6]), "=f"(v[7])
        : "l"(p));
}

__device__ __forceinline__ void stg256_cs(float* p, const float* v)
{
    asm volatile("st.global.cs.v8.f32 [%0], {%1,%2,%3,%4,%5,%6,%7,%8};"
        :: "l"(p),
           "f"(v[0]), "f"(v[1]), "f"(v[2]), "f"(v[3]),
           "f"(v[4]), "f"(v[5]), "f"(v[6]), "f"(v[7])
        : "memory");
}

__global__ __launch_bounds__(THREADS) void tmc_softmax_v8(
    const float* __restrict__ x, float* __restrict__ out)
{
    const int lane = threadIdx.x;
    const size_t row = blockIdx.x;

    const float* __restrict__ rgb = x + row * ROW_F_STRIDE;
    const float* __restrict__ dep = rgb + NUM_CLASSES;
    float* __restrict__ outp = out + row * NUM_CLASSES;

    const bool tail = (lane + 32 * FULL_ITERS) < V8_PER_ROW;   // lane < 29

    float ev[(FULL_ITERS + 1) * 8];
    float local = 0.f;

    #pragma unroll
    for (int i = 0; i < FULL_ITERS; i++) {
        const int idx = (lane + 32 * i) * 8;
        float r[8], d[8];
        ldg256_cs(rgb + idx, r);
        ldg256_cs(dep + idx, d);
        #pragma unroll
        for (int j = 0; j < 8; j++) {
            float e = __expf(fmaf(d[j] * r[j], 1e-3f, d[j] + r[j]));
            ev[i * 8 + j] = e;
            local += e;
        }
    }
    if (tail) {
        const int idx = (lane + 32 * FULL_ITERS) * 8;
        float r[8], d[8];
        ldg256_cs(rgb + idx, r);
        ldg256_cs(dep + idx, d);
        #pragma unroll
        for (int j = 0; j < 8; j++) {
            float e = __expf(fmaf(d[j] * r[j], 1e-3f, d[j] + r[j]));
            ev[FULL_ITERS * 8 + j] = e;
            local += e;
        }
    }

    // Warp-only reduction: no barriers, no smem.
    #pragma unroll
    for (int off = 16; off > 0; off >>= 1)
        local += __shfl_xor_sync(0xFFFFFFFFu, local, off);

    const float inv = 1.0f / local;

    #pragma unroll
    for (int i = 0; i < FULL_ITERS; i++) {
        const int idx = (lane + 32 * i) * 8;
        float o[8];
        #pragma unroll
        for (int j = 0; j < 8; j++) o[j] = ev[i * 8 + j] * inv;
        stg256_cs(outp + idx, o);
    }
    if (tail) {
        const int idx = (lane + 32 * FULL_ITERS) * 8;
        float o[8];
        #pragma unroll
        for (int j = 0; j < 8; j++) o[j] = ev[FULL_ITERS * 8 + j] * inv;
        stg256_cs(outp + idx, o);
    }
}

extern "C" void kernel_launch(void* const* d_in, const int* in_sizes, int n_in,
                              void* d_out, int out_size)
{
    const float* x = (const float*)d_in[0];
    float* out = (float*)d_out;
    const int batch = in_sizes[0] / ROW_F_STRIDE;   // 65536
    tmc_softmax_v8<<<batch, THREADS>>>(x, out);
}